// round 9
// baseline (speedup 1.0000x reference)
#include <cuda_runtime.h>
#include <cuda_bf16.h>

#define CI 16
#define CO 16
#define DEG 16
#define BSROW (1 + DEG)            // 17 ints per bs_slice row

#define THREADS 128
#define NITER 8
#define PTS_BLK (8 * NITER)        // 64 points per block
#define WPAD 52                    // per-lane W slice stride (floats): conflict-free

// out[p,o] = sum_j sum_d radii[p*DEG+j,d] * sum_i W[d,o,i] * features[nbr(p,j),i]
// Factored: g_d[i] = sum_j r_jd * f[nbr_j,i];  out[o] = sum_{d,i} W[d,o,i] * g_d[i]
//
// Fused, warp-native, pipelined:
//  - radii STAGED THROUGH SMEM in one bulk coalesced burst at entry (DRAM
//    latency paid once per block, per-iter consumption is LDS.128)
//  - all 8 iterations' neighbor-index words preloaded at entry
//  - features (the only per-iter global load) prefetched 1 iteration ahead
//  - phase 1 reduce over neighbor quads: shfl_xor(4),(8)
//  - phase 2: W slice from smem, reduce over c4: shfl_xor(1),(2)
__global__ __launch_bounds__(THREADS)
void PeriodicConvolutionPrep_fused(
    const float* __restrict__ features,   // [P, CI]
    const float* __restrict__ radii,      // [P*DEG, 3]
    const float* __restrict__ W,          // [3, CO, CI]
    const int*   __restrict__ bs,         // [P, 1+DEG]
    float*       __restrict__ out,        // [P, CO]
    int P)
{
    __shared__ float  s_w[16][WPAD];          // 3.25 KB
    __shared__ float4 s_r4[PTS_BLK * 12];     // 12 KB: radii, [localPt][q*3+k]

    const int tid   = threadIdx.x;
    const int t16   = tid & 15;
    const int q     = t16 >> 2;          // neighbor quad (ph1) / o-quad (ph2)
    const int c4    = t16 & 3;           // channel quad (ph1) / i-quad (ph2)
    const int pt    = tid >> 4;          // point group within block (0..7)
    const int lane  = tid & 31;
    const int gbase = lane & ~15;

    const int base   = blockIdx.x * PTS_BLK;
    const int nvalid = min(PTS_BLK, P - base);

    // ---- stage W slices (threads 0..15) ----
    if (tid < 16) {
        const int qq = tid >> 2, cc4 = tid & 3;
#pragma unroll
        for (int d = 0; d < 3; d++) {
#pragma unroll
            for (int oo = 0; oo < 4; oo++) {
                float4 v = __ldg((const float4*)(W + ((size_t)d * CO + 4 * qq + oo) * CI + 4 * cc4));
                *(float4*)&s_w[tid][d * 16 + oo * 4] = v;
            }
        }
    }

    // ---- bulk coalesced radii staging: nvalid*12 float4, decoupled loads ----
    {
        const float4* rsrc = (const float4*)(radii + (size_t)base * (DEG * 3));
        const int nf4 = nvalid * 12;
        for (int k = tid; k < nf4; k += THREADS)
            s_r4[k] = __ldg(rsrc + k);
    }

    // ---- point ids + preload ALL iterations' index words ----
    int  p[NITER];
    bool valid[NITER];
    int  myv[NITER];
#pragma unroll
    for (int it = 0; it < NITER; it++) {
        int pp = base + it * 8 + pt;
        valid[it] = (pp < P);
        p[it] = valid[it] ? pp : (P - 1);
        myv[it] = __ldg(bs + (size_t)p[it] * BSROW + 1 + t16);
    }

    __syncthreads();

    // ---- feature prefetch (double-buffered), only per-iter global load ----
    float4 fpre[2][4];
    const float4* fb4 = (const float4*)features;

    auto issue_gather = [&](int it, int slot) {
        const int m  = myv[it];
        const int i0 = __shfl_sync(0xffffffffu, m, gbase + 4 * q + 0);
        const int i1 = __shfl_sync(0xffffffffu, m, gbase + 4 * q + 1);
        const int i2 = __shfl_sync(0xffffffffu, m, gbase + 4 * q + 2);
        const int i3 = __shfl_sync(0xffffffffu, m, gbase + 4 * q + 3);
        fpre[slot][0] = __ldg(fb4 + (size_t)i0 * (CI / 4) + c4);
        fpre[slot][1] = __ldg(fb4 + (size_t)i1 * (CI / 4) + c4);
        fpre[slot][2] = __ldg(fb4 + (size_t)i2 * (CI / 4) + c4);
        fpre[slot][3] = __ldg(fb4 + (size_t)i3 * (CI / 4) + c4);
    };

    issue_gather(0, 0);

#pragma unroll
    for (int it = 0; it < NITER; it++) {
        const int slot = it & 1;
        if (it + 1 < NITER)
            issue_gather(it + 1, (it + 1) & 1);   // overlap next iter's gather

        const float4 f0 = fpre[slot][0];
        const float4 f1 = fpre[slot][1];
        const float4 f2 = fpre[slot][2];
        const float4 f3 = fpre[slot][3];

        // radii for this lane's quad from smem (broadcast across c4 lanes)
        const int lp = it * 8 + pt;               // local point id (valid-clamped grid)
        const float4 rv0 = s_r4[lp * 12 + q * 3 + 0];
        const float4 rv1 = s_r4[lp * 12 + q * 3 + 1];
        const float4 rv2 = s_r4[lp * 12 + q * 3 + 2];
        const float r[12] = { rv0.x, rv0.y, rv0.z, rv0.w, rv1.x, rv1.y,
                              rv1.z, rv1.w, rv2.x, rv2.y, rv2.z, rv2.w };

        // -- partial g[d][cc] over this lane's 4 neighbors: 48 FMA --
        float g[12];
#pragma unroll
        for (int d = 0; d < 3; d++) {
            g[d * 4 + 0] = r[0 * 3 + d] * f0.x;
            g[d * 4 + 1] = r[0 * 3 + d] * f0.y;
            g[d * 4 + 2] = r[0 * 3 + d] * f0.z;
            g[d * 4 + 3] = r[0 * 3 + d] * f0.w;
            g[d * 4 + 0] = fmaf(r[1 * 3 + d], f1.x, g[d * 4 + 0]);
            g[d * 4 + 1] = fmaf(r[1 * 3 + d], f1.y, g[d * 4 + 1]);
            g[d * 4 + 2] = fmaf(r[1 * 3 + d], f1.z, g[d * 4 + 2]);
            g[d * 4 + 3] = fmaf(r[1 * 3 + d], f1.w, g[d * 4 + 3]);
            g[d * 4 + 0] = fmaf(r[2 * 3 + d], f2.x, g[d * 4 + 0]);
            g[d * 4 + 1] = fmaf(r[2 * 3 + d], f2.y, g[d * 4 + 1]);
            g[d * 4 + 2] = fmaf(r[2 * 3 + d], f2.z, g[d * 4 + 2]);
            g[d * 4 + 3] = fmaf(r[2 * 3 + d], f2.w, g[d * 4 + 3]);
            g[d * 4 + 0] = fmaf(r[3 * 3 + d], f3.x, g[d * 4 + 0]);
            g[d * 4 + 1] = fmaf(r[3 * 3 + d], f3.y, g[d * 4 + 1]);
            g[d * 4 + 2] = fmaf(r[3 * 3 + d], f3.z, g[d * 4 + 2]);
            g[d * 4 + 3] = fmaf(r[3 * 3 + d], f3.w, g[d * 4 + 3]);
        }

        // -- reduce over q: every lane ends with full g_d[4c4..+3] --
#pragma unroll
        for (int v = 0; v < 12; v++) g[v] += __shfl_xor_sync(0xffffffffu, g[v], 4);
#pragma unroll
        for (int v = 0; v < 12; v++) g[v] += __shfl_xor_sync(0xffffffffu, g[v], 8);

        // -- Phase 2: o-quad q over i-quad c4: 12 LDS.128 + 48 FMA --
        float p0 = 0.f, p1 = 0.f, p2 = 0.f, p3 = 0.f;
#pragma unroll
        for (int d = 0; d < 3; d++) {
            float4 w0 = *(const float4*)&s_w[t16][d * 16 + 0];
            float4 w1 = *(const float4*)&s_w[t16][d * 16 + 4];
            float4 w2 = *(const float4*)&s_w[t16][d * 16 + 8];
            float4 w3 = *(const float4*)&s_w[t16][d * 16 + 12];
            const float g0 = g[d * 4 + 0], g1 = g[d * 4 + 1];
            const float g2 = g[d * 4 + 2], g3 = g[d * 4 + 3];
            p0 = fmaf(w0.x, g0, p0); p0 = fmaf(w0.y, g1, p0);
            p0 = fmaf(w0.z, g2, p0); p0 = fmaf(w0.w, g3, p0);
            p1 = fmaf(w1.x, g0, p1); p1 = fmaf(w1.y, g1, p1);
            p1 = fmaf(w1.z, g2, p1); p1 = fmaf(w1.w, g3, p1);
            p2 = fmaf(w2.x, g0, p2); p2 = fmaf(w2.y, g1, p2);
            p2 = fmaf(w2.z, g2, p2); p2 = fmaf(w2.w, g3, p2);
            p3 = fmaf(w3.x, g0, p3); p3 = fmaf(w3.y, g1, p3);
            p3 = fmaf(w3.z, g2, p3); p3 = fmaf(w3.w, g3, p3);
        }

        // -- reduce over c4 --
        p0 += __shfl_xor_sync(0xffffffffu, p0, 1);
        p1 += __shfl_xor_sync(0xffffffffu, p1, 1);
        p2 += __shfl_xor_sync(0xffffffffu, p2, 1);
        p3 += __shfl_xor_sync(0xffffffffu, p3, 1);
        p0 += __shfl_xor_sync(0xffffffffu, p0, 2);
        p1 += __shfl_xor_sync(0xffffffffu, p1, 2);
        p2 += __shfl_xor_sync(0xffffffffu, p2, 2);
        p3 += __shfl_xor_sync(0xffffffffu, p3, 2);

        const float res = (c4 == 0) ? p0 : (c4 == 1) ? p1 : (c4 == 2) ? p2 : p3;
        if (valid[it])
            out[(size_t)p[it] * CO + t16] = res;
    }
}

extern "C" void kernel_launch(void* const* d_in, const int* in_sizes, int n_in,
                              void* d_out, int out_size) {
    const float* features = (const float*)d_in[0];
    const float* radii    = (const float*)d_in[1];
    const float* W        = (const float*)d_in[2];
    const int*   bs       = (const int*)d_in[3];
    float*       out      = (float*)d_out;

    const int P = in_sizes[0] / CI;
    const int blocks = (P + PTS_BLK - 1) / PTS_BLK;   // 625 for P=40000
    PeriodicConvolutionPrep_fused<<<blocks, THREADS>>>(features, radii, W, bs, out, P);
}